// round 10
// baseline (speedup 1.0000x reference)
#include <cuda_runtime.h>
#include <cuda_fp16.h>
#include <math.h>

#define Bn 16
#define Tn 2048
#define Cn 384
#define Hn 64
#define BT (Bn*Tn)

// Projected Q (pre-scaled by log2e/sqrt(C)), K, V in fp16.
__device__ __half g_q[BT*Hn];
__device__ __half g_k[BT*Hn];
__device__ __half g_v[BT*Hn];

// ---------------- helpers ----------------
__device__ __forceinline__ unsigned smem_u32(const void* p) {
    return (unsigned)__cvta_generic_to_shared(p);
}
__device__ __forceinline__ unsigned f22u(float lo, float hi) {
    __half2 h = __floats2half2_rn(lo, hi);
    return *reinterpret_cast<unsigned*>(&h);
}
__device__ __forceinline__ void mma_f16(float* d, const unsigned* a, unsigned b0, unsigned b1) {
    asm("mma.sync.aligned.m16n8k16.row.col.f32.f16.f16.f32 "
        "{%0,%1,%2,%3}, {%4,%5,%6,%7}, {%8,%9}, {%0,%1,%2,%3};"
        : "+f"(d[0]), "+f"(d[1]), "+f"(d[2]), "+f"(d[3])
        : "r"(a[0]), "r"(a[1]), "r"(a[2]), "r"(a[3]), "r"(b0), "r"(b1));
}
__device__ __forceinline__ void mma_f16h(unsigned* d, const unsigned* a, unsigned b0, unsigned b1) {
    asm("mma.sync.aligned.m16n8k16.row.col.f16.f16.f16.f16 "
        "{%0,%1}, {%2,%3,%4,%5}, {%6,%7}, {%0,%1};"
        : "+r"(d[0]), "+r"(d[1])
        : "r"(a[0]), "r"(a[1]), "r"(a[2]), "r"(a[3]), "r"(b0), "r"(b1));
}
__device__ __forceinline__ void ldsm_x4(unsigned& r0, unsigned& r1, unsigned& r2, unsigned& r3, unsigned addr) {
    asm volatile("ldmatrix.sync.aligned.m8n8.x4.shared.b16 {%0,%1,%2,%3}, [%4];"
                 : "=r"(r0), "=r"(r1), "=r"(r2), "=r"(r3) : "r"(addr));
}
__device__ __forceinline__ void ldsm_x4_t(unsigned& r0, unsigned& r1, unsigned& r2, unsigned& r3, unsigned addr) {
    asm volatile("ldmatrix.sync.aligned.m8n8.x4.trans.shared.b16 {%0,%1,%2,%3}, [%4];"
                 : "=r"(r0), "=r"(r1), "=r"(r2), "=r"(r3) : "r"(addr));
}
__device__ __forceinline__ void cp16(unsigned saddr, const void* gaddr) {
    asm volatile("cp.async.cg.shared.global [%0], [%1], 16;" :: "r"(saddr), "l"(gaddr));
}

// ---------------- projection: single pass, N=192, double-buffered smem ----------------
#define PXS 40
#define PWS 200

__global__ __launch_bounds__(256) void proj_kernel(
    const float* __restrict__ x,
    const float* __restrict__ Wq,
    const float* __restrict__ Wk,
    const float* __restrict__ Wv)
{
    __shared__ __align__(16) __half xs[2][128 * PXS];
    __shared__ __align__(16) __half ws[2][32 * PWS];

    int tid = threadIdx.x;
    int w = tid >> 5, lane = tid & 31;
    int g = lane >> 2, tig = lane & 3;
    int rowbase = blockIdx.x * 128;
    int mb = w * 16;
    int lrow = lane & 15;
    int lcol = (lane >> 4) * 16;

    float acc[24][4];
    #pragma unroll
    for (int j = 0; j < 24; j++)
        #pragma unroll
        for (int i = 0; i < 4; i++) acc[j][i] = 0.f;

    float4 px[4];
    float2 pw[12];

    #pragma unroll
    for (int i = 0; i < 4; i++) {
        int flat = tid + 256 * i;
        int m = flat >> 3, c4 = (flat & 7) * 4;
        px[i] = *reinterpret_cast<const float4*>(&x[(size_t)(rowbase + m) * Cn + c4]);
    }
    #pragma unroll
    for (int i = 0; i < 12; i++) {
        int flat = tid + 256 * i;
        int k = flat / 96, c2 = (flat % 96) * 2;
        const float* W = (c2 < 64) ? Wq : (c2 < 128 ? Wk : Wv);
        pw[i] = *reinterpret_cast<const float2*>(&W[(size_t)k * Hn + (c2 & 63)]);
    }

    for (int c = 0; c < 12; c++) {
        __half* xb = xs[c & 1];
        __half* wb = ws[c & 1];
        unsigned xs_base = smem_u32(xb);
        unsigned ws_base = smem_u32(wb);
        #pragma unroll
        for (int i = 0; i < 4; i++) {
            int flat = tid + 256 * i;
            int m = flat >> 3, c4 = (flat & 7) * 4;
            *reinterpret_cast<uint2*>(&xb[m * PXS + c4]) =
                make_uint2(f22u(px[i].x, px[i].y), f22u(px[i].z, px[i].w));
        }
        #pragma unroll
        for (int i = 0; i < 12; i++) {
            int flat = tid + 256 * i;
            int k = flat / 96, c2 = (flat % 96) * 2;
            *reinterpret_cast<unsigned*>(&wb[k * PWS + c2]) = f22u(pw[i].x, pw[i].y);
        }
        __syncthreads();
        if (c < 11) {
            int k0 = (c + 1) * 32;
            #pragma unroll
            for (int i = 0; i < 4; i++) {
                int flat = tid + 256 * i;
                int m = flat >> 3, c4 = (flat & 7) * 4;
                px[i] = *reinterpret_cast<const float4*>(&x[(size_t)(rowbase + m) * Cn + k0 + c4]);
            }
            #pragma unroll
            for (int i = 0; i < 12; i++) {
                int flat = tid + 256 * i;
                int k = flat / 96, c2 = (flat % 96) * 2;
                const float* W = (c2 < 64) ? Wq : (c2 < 128 ? Wk : Wv);
                pw[i] = *reinterpret_cast<const float2*>(&W[(size_t)(k0 + k) * Hn + (c2 & 63)]);
            }
        }
        #pragma unroll
        for (int kk = 0; kk < 2; kk++) {
            unsigned af[4];
            ldsm_x4(af[0], af[1], af[2], af[3],
                    xs_base + (mb + lrow) * (PXS * 2) + kk * 32 + lcol);
            #pragma unroll
            for (int jj = 0; jj < 12; jj++) {
                unsigned r0, r1, r2, r3;
                ldsm_x4_t(r0, r1, r2, r3,
                          ws_base + (kk * 16 + lrow) * (PWS * 2) + jj * 32 + lcol);
                mma_f16(acc[2 * jj],     af, r0, r1);
                mma_f16(acc[2 * jj + 1], af, r2, r3);
            }
        }
    }

    const float qsc = rsqrtf((float)Cn) * 1.44269504f;
    size_t r0r = (size_t)(rowbase + mb + g);
    #pragma unroll
    for (int j = 0; j < 24; j++) {
        int gc = j * 8 + 2 * tig;
        __half* dst = (gc < 64) ? g_q : (gc < 128 ? g_k : g_v);
        float sc = (gc < 64) ? qsc : 1.f;
        int cc = gc & 63;
        *reinterpret_cast<unsigned*>(&dst[r0r * Hn + cc])       = f22u(acc[j][0] * sc, acc[j][1] * sc);
        *reinterpret_cast<unsigned*>(&dst[(r0r + 8) * Hn + cc]) = f22u(acc[j][2] * sc, acc[j][3] * sc);
    }
}

// ---------------- flash attention: cross-tile pipelined S(i+1)||PV(i), triple-buffered ----------------
#define ST 72                     // halfs per smem row (144B): conflict-free ldsm
#define TILE_H (64 * ST)          // one K or V tile (halfs)
#define PAIR_B (2 * TILE_H * 2)   // K+V pair bytes = 18432
#define A_SMEM (3 * PAIR_B)       // 55296 B
#define ONES2 0x3C003C00u

__global__ __launch_bounds__(128, 4) void attn_kernel(float* __restrict__ out)
{
    extern __shared__ __align__(16) __half sm[];

    int tid = threadIdx.x;
    int w = tid >> 5, lane = tid & 31;
    int g = lane >> 2, tig = lane & 3;
    int b = blockIdx.y;
    int qbase = blockIdx.x * 64;
    int mb = w * 16;
    int lrow = lane & 15;
    int lcol = (lane >> 4) * 16;

    const __half* qg = g_q + ((size_t)b * Tn + qbase) * Hn;
    const __half* kg = g_k + (size_t)b * Tn * Hn;
    const __half* vg = g_v + (size_t)b * Tn * Hn;
    unsigned sm_base = smem_u32(sm);

    // stage Q into buf2's K area (safe: qf loads are fenced before buf2 is first written at it=0)
    __half* qstage = sm + 2 * (2 * TILE_H);
    #pragma unroll
    for (int i = 0; i < 4; i++) {
        int flat = tid + 128 * i;
        int m = flat >> 3, c8 = (flat & 7) * 8;
        *reinterpret_cast<uint4*>(&qstage[m * ST + c8]) =
            *reinterpret_cast<const uint4*>(&qg[(size_t)m * Hn + c8]);
    }
    __syncthreads();
    unsigned qs_base = sm_base + 2 * PAIR_B;
    unsigned qf[4][4];
    #pragma unroll
    for (int kk = 0; kk < 4; kk++)
        ldsm_x4(qf[kk][0], qf[kk][1], qf[kk][2], qf[kk][3],
                qs_base + (mb + lrow) * (ST * 2) + kk * 32 + lcol);

    // issue tiles 0 and 1 into bufs 0 and 1
    #pragma unroll
    for (int t = 0; t < 2; t++) {
        unsigned kd = sm_base + t * PAIR_B;
        unsigned vd = kd + TILE_H * 2;
        const __half* kgs = kg + (size_t)t * 64 * Hn;
        const __half* vgs = vg + (size_t)t * 64 * Hn;
        #pragma unroll
        for (int i = 0; i < 4; i++) {
            int flat = tid + 128 * i;
            int n = flat >> 3, c8 = (flat & 7) * 8;
            cp16(kd + n * (ST * 2) + c8 * 2, &kgs[(size_t)n * Hn + c8]);
            cp16(vd + n * (ST * 2) + c8 * 2, &vgs[(size_t)n * Hn + c8]);
        }
        asm volatile("cp.async.commit_group;" ::: "memory");
    }
    asm volatile("cp.async.wait_group 1;" ::: "memory");   // tile 0 ready
    __syncthreads();

    // S(0) into sh[0]
    unsigned sh[2][8][2];
    #pragma unroll
    for (int j = 0; j < 8; j++) { sh[0][j][0] = 0u; sh[0][j][1] = 0u; }
    {
        unsigned ks = sm_base;
        #pragma unroll
        for (int kk = 0; kk < 4; kk++) {
            #pragma unroll
            for (int jj = 0; jj < 4; jj++) {
                unsigned r0, r1, r2, r3;
                ldsm_x4(r0, r1, r2, r3, ks + (jj * 16 + lrow) * (ST * 2) + kk * 32 + lcol);
                mma_f16h(sh[0][2 * jj],     qf[kk], r0, r2);
                mma_f16h(sh[0][2 * jj + 1], qf[kk], r1, r3);
            }
        }
    }

    float oacc[8][4];
    #pragma unroll
    for (int j = 0; j < 8; j++)
        #pragma unroll
        for (int i = 0; i < 4; i++) oacc[j][i] = 0.f;
    float oex[4] = {0.f, 0.f, 0.f, 0.f};

    const int NTILES = Tn / 64;
    for (int it = 0; it < NTILES; it++) {
        unsigned (*shc)[2] = sh[it & 1];
        unsigned (*shn)[2] = sh[(it + 1) & 1];
        bool hasNext = (it + 1 < NTILES);

        // exp in place: P(it) = 2^S(it); accumulator layout == PV A-fragment
        #pragma unroll
        for (int j = 0; j < 8; j++) {
            asm("ex2.approx.f16x2 %0, %0;" : "+r"(shc[j][0]));
            asm("ex2.approx.f16x2 %0, %0;" : "+r"(shc[j][1]));
        }

        __syncthreads();  // all warps done with PV(it-1) reads (buf it-1 free) and S(it) K reads

        if (it + 2 < NTILES) {
            unsigned kd = sm_base + ((it + 2) % 3) * PAIR_B;
            unsigned vd = kd + TILE_H * 2;
            const __half* kgs = kg + (size_t)(it + 2) * 64 * Hn;
            const __half* vgs = vg + (size_t)(it + 2) * 64 * Hn;
            #pragma unroll
            for (int i = 0; i < 4; i++) {
                int flat = tid + 128 * i;
                int n = flat >> 3, c8 = (flat & 7) * 8;
                cp16(kd + n * (ST * 2) + c8 * 2, &kgs[(size_t)n * Hn + c8]);
                cp16(vd + n * (ST * 2) + c8 * 2, &vgs[(size_t)n * Hn + c8]);
            }
            asm volatile("cp.async.commit_group;" ::: "memory");
        }
        if (hasNext) {
            if (it + 2 < NTILES)
                asm volatile("cp.async.wait_group 1;" ::: "memory");  // tile it+1 ready
            else
                asm volatile("cp.async.wait_group 0;" ::: "memory");
            __syncthreads();
            #pragma unroll
            for (int j = 0; j < 8; j++) { shn[j][0] = 0u; shn[j][1] = 0u; }
        }

        unsigned ksn = sm_base + ((it + 1) % 3) * PAIR_B;            // K(it+1)
        unsigned vsc = sm_base + (it % 3) * PAIR_B + TILE_H * 2;     // V(it)

        // interleaved: S(it+1) MMAs || PV(it) MMAs — independent streams
        #pragma unroll
        for (int kk = 0; kk < 4; kk++) {
            if (hasNext) {
                #pragma unroll
                for (int jj = 0; jj < 4; jj++) {
                    unsigned r0, r1, r2, r3;
                    ldsm_x4(r0, r1, r2, r3, ksn + (jj * 16 + lrow) * (ST * 2) + kk * 32 + lcol);
                    mma_f16h(shn[2 * jj],     qf[kk], r0, r2);
                    mma_f16h(shn[2 * jj + 1], qf[kk], r1, r3);
                }
            }
            unsigned pa[4];
            pa[0] = shc[2 * kk][0];
            pa[1] = shc[2 * kk][1];
            pa[2] = shc[2 * kk + 1][0];
            pa[3] = shc[2 * kk + 1][1];
            #pragma unroll
            for (int jj = 0; jj < 4; jj++) {
                unsigned r0, r1, r2, r3;
                ldsm_x4_t(r0, r1, r2, r3, vsc + (kk * 16 + lrow) * (ST * 2) + jj * 32 + lcol);
                mma_f16(oacc[2 * jj],     pa, r0, r1);
                mma_f16(oacc[2 * jj + 1], pa, r2, r3);
            }
            mma_f16(oex, pa, ONES2, ONES2);
        }
    }

    // epilogue: each lane holds full row sums (ones-MMA columns identical)
    float inv0 = 1.f / oex[0];
    float inv1 = 1.f / oex[2];
    float* og = out + ((size_t)b * Tn + qbase) * Hn;
    size_t r0r = (size_t)(mb + g);
    #pragma unroll
    for (int j = 0; j < 8; j++) {
        int c = j * 8 + 2 * tig;
        *reinterpret_cast<float2*>(&og[r0r * Hn + c]) =
            make_float2(oacc[j][0] * inv0, oacc[j][1] * inv0);
        *reinterpret_cast<float2*>(&og[(r0r + 8) * Hn + c]) =
            make_float2(oacc[j][2] * inv1, oacc[j][3] * inv1);
    }
}

// ---------------- launch ----------------
extern "C" void kernel_launch(void* const* d_in, const int* in_sizes, int n_in,
                              void* d_out, int out_size)
{
    const float* x  = (const float*)d_in[0];
    const float* Wq = (const float*)d_in[1];
    const float* Wk = (const float*)d_in[2];
    const float* Wv = (const float*)d_in[3];
    float* out = (float*)d_out;

    cudaFuncSetAttribute(attn_kernel, cudaFuncAttributeMaxDynamicSharedMemorySize, A_SMEM);

    proj_kernel<<<BT / 128, 256>>>(x, Wq, Wk, Wv);
    attn_kernel<<<dim3(Tn / 64, Bn), 128, A_SMEM>>>(out);
}

// round 11
// speedup vs baseline: 2.1966x; 2.1966x over previous
#include <cuda_runtime.h>
#include <cuda_fp16.h>
#include <math.h>

#define Bn 16
#define Tn 2048
#define Cn 384
#define Hn 64
#define BT (Bn*Tn)

// Projected Q (pre-scaled by log2e/sqrt(C)), K, V in fp16.
__device__ __half g_q[BT*Hn];
__device__ __half g_k[BT*Hn];
__device__ __half g_v[BT*Hn];

// ---------------- helpers ----------------
__device__ __forceinline__ unsigned smem_u32(const void* p) {
    return (unsigned)__cvta_generic_to_shared(p);
}
__device__ __forceinline__ unsigned f22u(float lo, float hi) {
    __half2 h = __floats2half2_rn(lo, hi);
    return *reinterpret_cast<unsigned*>(&h);
}
__device__ __forceinline__ void mma_f16(float* d, const unsigned* a, unsigned b0, unsigned b1) {
    asm("mma.sync.aligned.m16n8k16.row.col.f32.f16.f16.f32 "
        "{%0,%1,%2,%3}, {%4,%5,%6,%7}, {%8,%9}, {%0,%1,%2,%3};"
        : "+f"(d[0]), "+f"(d[1]), "+f"(d[2]), "+f"(d[3])
        : "r"(a[0]), "r"(a[1]), "r"(a[2]), "r"(a[3]), "r"(b0), "r"(b1));
}
__device__ __forceinline__ void mma_f16h(unsigned* d, const unsigned* a, unsigned b0, unsigned b1) {
    asm("mma.sync.aligned.m16n8k16.row.col.f16.f16.f16.f16 "
        "{%0,%1}, {%2,%3,%4,%5}, {%6,%7}, {%0,%1};"
        : "+r"(d[0]), "+r"(d[1])
        : "r"(a[0]), "r"(a[1]), "r"(a[2]), "r"(a[3]), "r"(b0), "r"(b1));
}
__device__ __forceinline__ void ldsm_x4(unsigned& r0, unsigned& r1, unsigned& r2, unsigned& r3, unsigned addr) {
    asm volatile("ldmatrix.sync.aligned.m8n8.x4.shared.b16 {%0,%1,%2,%3}, [%4];"
                 : "=r"(r0), "=r"(r1), "=r"(r2), "=r"(r3) : "r"(addr));
}
__device__ __forceinline__ void ldsm_x4_t(unsigned& r0, unsigned& r1, unsigned& r2, unsigned& r3, unsigned addr) {
    asm volatile("ldmatrix.sync.aligned.m8n8.x4.trans.shared.b16 {%0,%1,%2,%3}, [%4];"
                 : "=r"(r0), "=r"(r1), "=r"(r2), "=r"(r3) : "r"(addr));
}
__device__ __forceinline__ void cp16(unsigned saddr, const void* gaddr) {
    asm volatile("cp.async.cg.shared.global [%0], [%1], 16;" :: "r"(saddr), "l"(gaddr));
}

// ---------------- projection: single pass, N=192, double-buffered smem ----------------
#define PXS 40    // halfs/row (80B): conflict-free ldsm
#define PWS 200   // halfs/row (400B): conflict-free ldsm.t

__global__ __launch_bounds__(256) void proj_kernel(
    const float* __restrict__ x,
    const float* __restrict__ Wq,
    const float* __restrict__ Wk,
    const float* __restrict__ Wv)
{
    __shared__ __align__(16) __half xs[2][128 * PXS];
    __shared__ __align__(16) __half ws[2][32 * PWS];

    int tid = threadIdx.x;
    int w = tid >> 5, lane = tid & 31;
    int g = lane >> 2, tig = lane & 3;
    int rowbase = blockIdx.x * 128;
    int mb = w * 16;
    int lrow = lane & 15;
    int lcol = (lane >> 4) * 16;

    float acc[24][4];
    #pragma unroll
    for (int j = 0; j < 24; j++)
        #pragma unroll
        for (int i = 0; i < 4; i++) acc[j][i] = 0.f;

    float4 px[4];
    float2 pw[12];

    #pragma unroll
    for (int i = 0; i < 4; i++) {
        int flat = tid + 256 * i;
        int m = flat >> 3, c4 = (flat & 7) * 4;
        px[i] = *reinterpret_cast<const float4*>(&x[(size_t)(rowbase + m) * Cn + c4]);
    }
    #pragma unroll
    for (int i = 0; i < 12; i++) {
        int flat = tid + 256 * i;
        int k = flat / 96, c2 = (flat % 96) * 2;
        const float* W = (c2 < 64) ? Wq : (c2 < 128 ? Wk : Wv);
        pw[i] = *reinterpret_cast<const float2*>(&W[(size_t)k * Hn + (c2 & 63)]);
    }

    for (int c = 0; c < 12; c++) {
        __half* xb = xs[c & 1];
        __half* wb = ws[c & 1];
        unsigned xs_base = smem_u32(xb);
        unsigned ws_base = smem_u32(wb);
        #pragma unroll
        for (int i = 0; i < 4; i++) {
            int flat = tid + 256 * i;
            int m = flat >> 3, c4 = (flat & 7) * 4;
            *reinterpret_cast<uint2*>(&xb[m * PXS + c4]) =
                make_uint2(f22u(px[i].x, px[i].y), f22u(px[i].z, px[i].w));
        }
        #pragma unroll
        for (int i = 0; i < 12; i++) {
            int flat = tid + 256 * i;
            int k = flat / 96, c2 = (flat % 96) * 2;
            *reinterpret_cast<unsigned*>(&wb[k * PWS + c2]) = f22u(pw[i].x, pw[i].y);
        }
        __syncthreads();
        if (c < 11) {
            int k0 = (c + 1) * 32;
            #pragma unroll
            for (int i = 0; i < 4; i++) {
                int flat = tid + 256 * i;
                int m = flat >> 3, c4 = (flat & 7) * 4;
                px[i] = *reinterpret_cast<const float4*>(&x[(size_t)(rowbase + m) * Cn + k0 + c4]);
            }
            #pragma unroll
            for (int i = 0; i < 12; i++) {
                int flat = tid + 256 * i;
                int k = flat / 96, c2 = (flat % 96) * 2;
                const float* W = (c2 < 64) ? Wq : (c2 < 128 ? Wk : Wv);
                pw[i] = *reinterpret_cast<const float2*>(&W[(size_t)(k0 + k) * Hn + (c2 & 63)]);
            }
        }
        #pragma unroll
        for (int kk = 0; kk < 2; kk++) {
            unsigned af[4];
            ldsm_x4(af[0], af[1], af[2], af[3],
                    xs_base + (mb + lrow) * (PXS * 2) + kk * 32 + lcol);
            #pragma unroll
            for (int jj = 0; jj < 12; jj++) {
                unsigned r0, r1, r2, r3;
                ldsm_x4_t(r0, r1, r2, r3,
                          ws_base + (kk * 16 + lrow) * (PWS * 2) + jj * 32 + lcol);
                mma_f16(acc[2 * jj],     af, r0, r1);
                mma_f16(acc[2 * jj + 1], af, r2, r3);
            }
        }
    }

    const float qsc = rsqrtf((float)Cn) * 1.44269504f;
    size_t r0r = (size_t)(rowbase + mb + g);
    #pragma unroll
    for (int j = 0; j < 24; j++) {
        int gc = j * 8 + 2 * tig;
        __half* dst = (gc < 64) ? g_q : (gc < 128 ? g_k : g_v);
        float sc = (gc < 64) ? qsc : 1.f;
        int cc = gc & 63;
        *reinterpret_cast<unsigned*>(&dst[r0r * Hn + cc])       = f22u(acc[j][0] * sc, acc[j][1] * sc);
        *reinterpret_cast<unsigned*>(&dst[(r0r + 8) * Hn + cc]) = f22u(acc[j][2] * sc, acc[j][3] * sc);
    }
}

// ---------------- flash attention: half-tile pipelined S(h1)||PV(h0), double-buffered ----------------
#define ST 72                    // halfs per smem row (144B): conflict-free ldsm
#define TILE_H (64 * ST)
#define ONES2 0x3C003C00u        // half2(1.0, 1.0)

__global__ __launch_bounds__(128, 5) void attn_kernel(float* __restrict__ out)
{
    __shared__ __align__(16) __half sm[4 * TILE_H];  // [buf][K|V]

    int tid = threadIdx.x;
    int w = tid >> 5, lane = tid & 31;
    int g = lane >> 2, tig = lane & 3;
    int b = blockIdx.y;
    int qbase = blockIdx.x * 64;
    int mb = w * 16;
    int lrow = lane & 15;
    int lcol = (lane >> 4) * 16;

    const __half* qg = g_q + ((size_t)b * Tn + qbase) * Hn;
    const __half* kg = g_k + (size_t)b * Tn * Hn;
    const __half* vg = g_v + (size_t)b * Tn * Hn;
    unsigned sm_base = smem_u32(sm);

    // stage Q (64x64 halfs)
    #pragma unroll
    for (int i = 0; i < 4; i++) {
        int flat = tid + 128 * i;
        int m = flat >> 3, c8 = (flat & 7) * 8;
        *reinterpret_cast<uint4*>(&sm[m * ST + c8]) =
            *reinterpret_cast<const uint4*>(&qg[(size_t)m * Hn + c8]);
    }
    __syncthreads();

    unsigned qf[4][4];
    #pragma unroll
    for (int kk = 0; kk < 4; kk++)
        ldsm_x4(qf[kk][0], qf[kk][1], qf[kk][2], qf[kk][3],
                sm_base + (mb + lrow) * (ST * 2) + kk * 32 + lcol);
    __syncthreads();  // Q reads done before cp.async overwrites

    // issue tile 0 into buf 0
    {
        unsigned kd = sm_base;
        unsigned vd = sm_base + TILE_H * 2;
        #pragma unroll
        for (int i = 0; i < 4; i++) {
            int flat = tid + 128 * i;
            int n = flat >> 3, c8 = (flat & 7) * 8;
            cp16(kd + n * (ST * 2) + c8 * 2, &kg[(size_t)n * Hn + c8]);
            cp16(vd + n * (ST * 2) + c8 * 2, &vg[(size_t)n * Hn + c8]);
        }
        asm volatile("cp.async.commit_group;" ::: "memory");
    }

    float oacc[8][4];
    #pragma unroll
    for (int j = 0; j < 8; j++)
        #pragma unroll
        for (int i = 0; i < 4; i++) oacc[j][i] = 0.f;
    float oex[4] = {0.f, 0.f, 0.f, 0.f};   // tensor-core row sums

    const int NTILES = Tn / 64;
    for (int it = 0; it < NTILES; it++) {
        asm volatile("cp.async.wait_group 0;" ::: "memory");
        __syncthreads();

        if (it + 1 < NTILES) {
            int nb = (it + 1) & 1;
            unsigned kd = sm_base + nb * 2 * TILE_H * 2;
            unsigned vd = kd + TILE_H * 2;
            const __half* kgs = kg + (size_t)(it + 1) * 64 * Hn;
            const __half* vgs = vg + (size_t)(it + 1) * 64 * Hn;
            #pragma unroll
            for (int i = 0; i < 4; i++) {
                int flat = tid + 128 * i;
                int n = flat >> 3, c8 = (flat & 7) * 8;
                cp16(kd + n * (ST * 2) + c8 * 2, &kgs[(size_t)n * Hn + c8]);
                cp16(vd + n * (ST * 2) + c8 * 2, &vgs[(size_t)n * Hn + c8]);
            }
            asm volatile("cp.async.commit_group;" ::: "memory");
        }

        unsigned ks = sm_base + (it & 1) * 2 * TILE_H * 2;
        unsigned vs = ks + TILE_H * 2;

        unsigned sh[8][2];
        #pragma unroll
        for (int j = 0; j < 8; j++) { sh[j][0] = 0u; sh[j][1] = 0u; }

        // ---- S half0: keys 0..31 (jj = 0,1) ----
        #pragma unroll
        for (int kk = 0; kk < 4; kk++) {
            #pragma unroll
            for (int jj = 0; jj < 2; jj++) {
                unsigned r0, r1, r2, r3;
                ldsm_x4(r0, r1, r2, r3,
                        ks + (jj * 16 + lrow) * (ST * 2) + kk * 32 + lcol);
                mma_f16h(sh[2 * jj],     qf[kk], r0, r2);
                mma_f16h(sh[2 * jj + 1], qf[kk], r1, r3);
            }
        }
        // ---- exp half0 ----
        #pragma unroll
        for (int j = 0; j < 4; j++) {
            asm("ex2.approx.f16x2 %0, %0;" : "+r"(sh[j][0]));
            asm("ex2.approx.f16x2 %0, %0;" : "+r"(sh[j][1]));
        }
        // ---- S half1 (keys 32..63) || PV half0 — independent streams, one unrolled block ----
        #pragma unroll
        for (int kk = 0; kk < 4; kk++) {
            #pragma unroll
            for (int jj = 2; jj < 4; jj++) {
                unsigned r0, r1, r2, r3;
                ldsm_x4(r0, r1, r2, r3,
                        ks + (jj * 16 + lrow) * (ST * 2) + kk * 32 + lcol);
                mma_f16h(sh[2 * jj],     qf[kk], r0, r2);
                mma_f16h(sh[2 * jj + 1], qf[kk], r1, r3);
            }
        }
        #pragma unroll
        for (int kks = 0; kks < 2; kks++) {
            unsigned pa[4];
            pa[0] = sh[2 * kks][0];
            pa[1] = sh[2 * kks][1];
            pa[2] = sh[2 * kks + 1][0];
            pa[3] = sh[2 * kks + 1][1];
            #pragma unroll
            for (int jj = 0; jj < 4; jj++) {
                unsigned r0, r1, r2, r3;
                ldsm_x4_t(r0, r1, r2, r3,
                          vs + (kks * 16 + lrow) * (ST * 2) + jj * 32 + lcol);
                mma_f16(oacc[2 * jj],     pa, r0, r1);
                mma_f16(oacc[2 * jj + 1], pa, r2, r3);
            }
            mma_f16(oex, pa, ONES2, ONES2);
        }
        // ---- exp half1 ----
        #pragma unroll
        for (int j = 4; j < 8; j++) {
            asm("ex2.approx.f16x2 %0, %0;" : "+r"(sh[j][0]));
            asm("ex2.approx.f16x2 %0, %0;" : "+r"(sh[j][1]));
        }
        // ---- PV half1 ----
        #pragma unroll
        for (int kks = 2; kks < 4; kks++) {
            unsigned pa[4];
            pa[0] = sh[2 * kks][0];
            pa[1] = sh[2 * kks][1];
            pa[2] = sh[2 * kks + 1][0];
            pa[3] = sh[2 * kks + 1][1];
            #pragma unroll
            for (int jj = 0; jj < 4; jj++) {
                unsigned r0, r1, r2, r3;
                ldsm_x4_t(r0, r1, r2, r3,
                          vs + (kks * 16 + lrow) * (ST * 2) + jj * 32 + lcol);
                mma_f16(oacc[2 * jj],     pa, r0, r1);
                mma_f16(oacc[2 * jj + 1], pa, r2, r3);
            }
            mma_f16(oex, pa, ONES2, ONES2);
        }
    }

    // epilogue: each lane holds full row sums (ones-MMA columns identical)
    float inv0 = 1.f / oex[0];
    float inv1 = 1.f / oex[2];
    float* og = out + ((size_t)b * Tn + qbase) * Hn;
    size_t r0r = (size_t)(mb + g);
    #pragma unroll
    for (int j = 0; j < 8; j++) {
        int c = j * 8 + 2 * tig;
        *reinterpret_cast<float2*>(&og[r0r * Hn + c]) =
            make_float2(oacc[j][0] * inv0, oacc[j][1] * inv0);
        *reinterpret_cast<float2*>(&og[(r0r + 8) * Hn + c]) =
            make_float2(oacc[j][2] * inv1, oacc[j][3] * inv1);
    }
}

// ---------------- launch ----------------
extern "C" void kernel_launch(void* const* d_in, const int* in_sizes, int n_in,
                              void* d_out, int out_size)
{
    const float* x  = (const float*)d_in[0];
    const float* Wq = (const float*)d_in[1];
    const float* Wk = (const float*)d_in[2];
    const float* Wv = (const float*)d_in[3];
    float* out = (float*)d_out;

    proj_kernel<<<BT / 128, 256>>>(x, Wq, Wk, Wv);
    attn_kernel<<<dim3(Tn / 64, Bn), 128>>>(out);
}